// round 5
// baseline (speedup 1.0000x reference)
#include <cuda_runtime.h>
#include <math.h>

// ---------------- problem constants ----------------
#define Bc   8
#define Pc   50
#define Nc   128
#define Mc   128
#define Hc   8
#define Dc   16
#define HDc  128          // H*D
#define NEc  8
#define Fc   129          // EMB+1
#define Tc   51200        // B*P*N
#define BPc  400          // B*P
#define GBc  6400         // gate blocks (T/8)

// ---------------- scratch (device globals; no allocs allowed) ----------------
__device__ float g_q  [Tc * HDc];
__device__ float g_k  [Tc * HDc];
__device__ float g_v  [Tc * HDc];
__device__ float g_att[Tc * HDc];         // out_concat
__device__ float g_moe[Tc * Fc];          // moe output (atomicAdd target)
__device__ int   g_cnt [NEc];
__device__ int   g_ltok[NEc * Tc];
__device__ float g_lg  [NEc * Tc];
__device__ float g_imp [GBc * NEc];       // per-block importance partials

// ---------------- 0: zero scratch that must start at 0 ----------------
__global__ void zero_kernel() {
    int i = blockIdx.x * 256 + threadIdx.x;   // grid covers exactly Tc*Fc
    g_moe[i] = 0.0f;
    if (i < NEc) g_cnt[i] = 0;
}

// ---------------- 1: QKV projections (shared-mem SGEMM) ----------------
// grid.x: [0,400) Q (F=128), [400,800) K (F=129), [800,1200) V (F=129)
// block: 256 threads, each computes 8x8 of a 128(rows)x128(cols) tile.
__global__ __launch_bounds__(256) void proj_kernel(
    const float* __restrict__ nodes, const float* __restrict__ routes,
    const float* __restrict__ Wq, const float* __restrict__ Wk,
    const float* __restrict__ Wv)
{
    int part = blockIdx.x / BPc;
    int tile = blockIdx.x % BPc;
    const float* X; const float* W; float* O; int F;
    if (part == 0)      { X = nodes;  W = Wq; O = g_q; F = 128; }
    else if (part == 1) { X = routes; W = Wk; O = g_k; F = Fc;  }
    else                { X = routes; W = Wv; O = g_v; F = Fc;  }

    extern __shared__ float sm[];
    float* Ws = sm;                  // [F][128]           (pitch 128)
    float* Xs = sm + Fc * 128;       // [F][132] transposed X (pitch 132, 16B-aligned)

    int tid = threadIdx.x;
    for (int i = tid; i < F * 128; i += 256) Ws[i] = W[i];
    const float* Xb = X + (size_t)tile * 128 * F;
    for (int i = tid; i < 128 * F; i += 256) {
        int r = i / F, f = i % F;
        Xs[f * 132 + r] = Xb[(size_t)r * F + f];
    }
    __syncthreads();

    int tx = tid & 15, ty = tid >> 4;
    int rb = ty * 8, cb = tx * 8;
    float acc[8][8];
#pragma unroll
    for (int i = 0; i < 8; i++)
#pragma unroll
        for (int j = 0; j < 8; j++) acc[i][j] = 0.0f;

#pragma unroll 4
    for (int f = 0; f < 128; ++f) {
        float4 t0 = *(const float4*)(Xs + f * 132 + rb);
        float4 t1 = *(const float4*)(Xs + f * 132 + rb + 4);
        float4 u0 = *(const float4*)(Ws + f * 128 + cb);
        float4 u1 = *(const float4*)(Ws + f * 128 + cb + 4);
        float a[8] = {t0.x, t0.y, t0.z, t0.w, t1.x, t1.y, t1.z, t1.w};
        float b[8] = {u0.x, u0.y, u0.z, u0.w, u1.x, u1.y, u1.z, u1.w};
#pragma unroll
        for (int i = 0; i < 8; i++)
#pragma unroll
            for (int j = 0; j < 8; j++) acc[i][j] = fmaf(a[i], b[j], acc[i][j]);
    }
    if (F > 128) {  // f = 128 tail for the 129-dim inputs
        int f = 128;
        float4 t0 = *(const float4*)(Xs + f * 132 + rb);
        float4 t1 = *(const float4*)(Xs + f * 132 + rb + 4);
        float4 u0 = *(const float4*)(Ws + f * 128 + cb);
        float4 u1 = *(const float4*)(Ws + f * 128 + cb + 4);
        float a[8] = {t0.x, t0.y, t0.z, t0.w, t1.x, t1.y, t1.z, t1.w};
        float b[8] = {u0.x, u0.y, u0.z, u0.w, u1.x, u1.y, u1.z, u1.w};
#pragma unroll
        for (int i = 0; i < 8; i++)
#pragma unroll
            for (int j = 0; j < 8; j++) acc[i][j] = fmaf(a[i], b[j], acc[i][j]);
    }

    float* Ob = O + (size_t)tile * 128 * HDc;
#pragma unroll
    for (int i = 0; i < 8; i++) {
        *(float4*)(Ob + (size_t)(rb + i) * HDc + cb) =
            make_float4(acc[i][0], acc[i][1], acc[i][2], acc[i][3]);
        *(float4*)(Ob + (size_t)(rb + i) * HDc + cb + 4) =
            make_float4(acc[i][4], acc[i][5], acc[i][6], acc[i][7]);
    }
}

// ---------------- 2: attention per (bp, head) ----------------
// block = 128 threads (one per query row). smem: k(128x16), v(128x16), S(128x129)
__global__ __launch_bounds__(128) void attn_kernel(
    const float* __restrict__ route_mask, const float* __restrict__ ninf)
{
    int bp = blockIdx.x, h = blockIdx.y;
    extern __shared__ float sm[];
    float* ks = sm;          // 2048
    float* vs = sm + 2048;   // 2048
    float* Ss = sm + 4096;   // 128*129

    int n = threadIdx.x;
    size_t tb = (size_t)bp * 128;

    // q row -> regs; k/v row n -> smem
    const float* qp = g_q + (tb + n) * HDc + h * Dc;
    float4 q0 = ((const float4*)qp)[0], q1 = ((const float4*)qp)[1];
    float4 q2 = ((const float4*)qp)[2], q3 = ((const float4*)qp)[3];
    float qr[16] = {q0.x,q0.y,q0.z,q0.w, q1.x,q1.y,q1.z,q1.w,
                    q2.x,q2.y,q2.z,q2.w, q3.x,q3.y,q3.z,q3.w};
    {
        const float4* kp = (const float4*)(g_k + (tb + n) * HDc + h * Dc);
        const float4* vp = (const float4*)(g_v + (tb + n) * HDc + h * Dc);
        float4* kd = (float4*)(ks + n * 16);
        float4* vd = (float4*)(vs + n * 16);
#pragma unroll
        for (int j = 0; j < 4; j++) { kd[j] = kp[j]; vd[j] = vp[j]; }
    }
    // route_mask tile -> Ss (coalesced)
    const float* rm = route_mask + (size_t)bp * 128 * 128;
    for (int i = n; i < 128 * 128; i += 128) {
        int r = i >> 7, m = i & 127;
        Ss[r * 129 + m] = rm[i];
    }
    __syncthreads();

    // scores
#pragma unroll 4
    for (int m = 0; m < 128; ++m) {
        const float4* kp = (const float4*)(ks + m * 16);
        float4 k0 = kp[0], k1 = kp[1], k2 = kp[2], k3 = kp[3];
        float s = qr[0]*k0.x + qr[1]*k0.y + qr[2]*k0.z + qr[3]*k0.w
                + qr[4]*k1.x + qr[5]*k1.y + qr[6]*k1.z + qr[7]*k1.w
                + qr[8]*k2.x + qr[9]*k2.y + qr[10]*k2.z + qr[11]*k2.w
                + qr[12]*k3.x + qr[13]*k3.y + qr[14]*k3.z + qr[15]*k3.w;
        Ss[n * 129 + m] = s * 0.25f + Ss[n * 129 + m];
    }

    // softmax (own row) fused with P@V
    float mx = -1e30f;
    for (int m = 0; m < 128; ++m) mx = fmaxf(mx, Ss[n * 129 + m]);
    float sum = 0.0f;
    float acc[16];
#pragma unroll
    for (int d = 0; d < 16; d++) acc[d] = 0.0f;
#pragma unroll 2
    for (int m = 0; m < 128; ++m) {
        float pe = __expf(Ss[n * 129 + m] - mx);
        sum += pe;
        const float4* vp = (const float4*)(vs + m * 16);
        float4 v0 = vp[0], v1 = vp[1], v2 = vp[2], v3 = vp[3];
        acc[0]+=pe*v0.x; acc[1]+=pe*v0.y; acc[2]+=pe*v0.z; acc[3]+=pe*v0.w;
        acc[4]+=pe*v1.x; acc[5]+=pe*v1.y; acc[6]+=pe*v1.z; acc[7]+=pe*v1.w;
        acc[8]+=pe*v2.x; acc[9]+=pe*v2.y; acc[10]+=pe*v2.z; acc[11]+=pe*v2.w;
        acc[12]+=pe*v3.x; acc[13]+=pe*v3.y; acc[14]+=pe*v3.z; acc[15]+=pe*v3.w;
    }
    float keep = (ninf[tb + n] == 0.0f) ? 1.0f : 0.0f;
    float inv = keep / sum;
    float* op = g_att + (tb + n) * HDc + h * Dc;
    ((float4*)op)[0] = make_float4(acc[0]*inv, acc[1]*inv, acc[2]*inv, acc[3]*inv);
    ((float4*)op)[1] = make_float4(acc[4]*inv, acc[5]*inv, acc[6]*inv, acc[7]*inv);
    ((float4*)op)[2] = make_float4(acc[8]*inv, acc[9]*inv, acc[10]*inv, acc[11]*inv);
    ((float4*)op)[3] = make_float4(acc[12]*inv, acc[13]*inv, acc[14]*inv, acc[15]*inv);
}

// ---------------- 3: gating (top-2 of 8) ----------------
// block = 256 threads = 8 warps, one token per warp
__global__ __launch_bounds__(256) void gate_kernel(const float* __restrict__ Wg)
{
    __shared__ float Wgs[NEc * 132];   // transposed [e][f], pitch 132
    __shared__ int   sE[8][2];
    __shared__ float sG[8][2];
    int tid = threadIdx.x, w = tid >> 5, l = tid & 31;

    for (int i = tid; i < NEc * 128; i += 256) {
        int e = i >> 7, f = i & 127;
        Wgs[e * 132 + f] = Wg[f * NEc + e];
    }
    __syncthreads();

    int t = blockIdx.x * 8 + w;
    float4 xv = *(const float4*)(g_att + (size_t)t * HDc + l * 4);
    float p[NEc];
#pragma unroll
    for (int e = 0; e < NEc; e++) {
        float4 wv = *(const float4*)(Wgs + e * 132 + l * 4);
        p[e] = xv.x*wv.x + xv.y*wv.y + xv.z*wv.z + xv.w*wv.w;
    }
#pragma unroll
    for (int off = 16; off > 0; off >>= 1)
#pragma unroll
        for (int e = 0; e < NEc; e++) p[e] += __shfl_xor_sync(0xffffffffu, p[e], off);

    if (l == 0) {
        float v1 = -1e30f, v2 = -1e30f; int i1 = 0, i2 = 0;
#pragma unroll
        for (int e = 0; e < NEc; e++) {
            float v = p[e];
            if (v > v1)      { v2 = v1; i2 = i1; v1 = v; i1 = e; }
            else if (v > v2) { v2 = v;  i2 = e; }
        }
        float e2x = __expf(v2 - v1);
        float den = 1.0f + e2x;
        float g1 = 1.0f / den, g2 = e2x / den;
        int s1 = atomicAdd(&g_cnt[i1], 1);
        g_ltok[i1 * Tc + s1] = t; g_lg[i1 * Tc + s1] = g1;
        int s2 = atomicAdd(&g_cnt[i2], 1);
        g_ltok[i2 * Tc + s2] = t; g_lg[i2 * Tc + s2] = g2;
        sE[w][0] = i1; sG[w][0] = g1; sE[w][1] = i2; sG[w][1] = g2;
    }
    __syncthreads();
    if (tid == 0) {  // fixed-order, deterministic importance partial
        float imp[NEc];
#pragma unroll
        for (int e = 0; e < NEc; e++) imp[e] = 0.0f;
        for (int ww = 0; ww < 8; ww++) {
            imp[sE[ww][0]] += sG[ww][0];
            imp[sE[ww][1]] += sG[ww][1];
        }
#pragma unroll
        for (int e = 0; e < NEc; e++) g_imp[blockIdx.x * NEc + e] = imp[e];
    }
}

// ---------------- 4: MoE expert GEMM (only top-2 experts per token) ----------------
// grid (chunks=800, experts=8); block 256; 64 tokens per block
__global__ __launch_bounds__(256) void moe_kernel(
    const float* __restrict__ We, const float* __restrict__ be)
{
    int e = blockIdx.y;
    int cnt = g_cnt[e];
    int base = blockIdx.x * 64;
    if (base >= cnt) return;
    int nt = min(64, cnt - base);

    extern __shared__ float sm[];
    float* Ws = sm;                 // [128][132]  (We[e], pitch 132)
    float* Xs = sm + 128 * 132;     // [128][68]   (transposed gathered x, pitch 68)
    __shared__ int   stok[64];
    __shared__ float sg[64];

    int tid = threadIdx.x;
    if (tid < 64) {
        if (tid < nt) { stok[tid] = g_ltok[e * Tc + base + tid];
                        sg[tid]   = g_lg  [e * Tc + base + tid]; }
        else          { stok[tid] = 0; sg[tid] = 0.0f; }
    }
    __syncthreads();

    const float* Wb = We + (size_t)e * 128 * Fc;
    for (int i = tid; i < 128 * Fc; i += 256) {
        int f = i / Fc, o = i % Fc;
        Ws[f * 132 + o] = Wb[i];
    }
    for (int i = tid; i < nt * 32; i += 256) {     // 32 float4 per token row
        int tk = i >> 5, c = i & 31;
        float4 v = *(const float4*)(g_att + (size_t)stok[tk] * HDc + c * 4);
        Xs[(c * 4 + 0) * 68 + tk] = v.x;
        Xs[(c * 4 + 1) * 68 + tk] = v.y;
        Xs[(c * 4 + 2) * 68 + tk] = v.z;
        Xs[(c * 4 + 3) * 68 + tk] = v.w;
    }
    __syncthreads();

    int tx = tid & 15, ty = tid >> 4;
    int tb = ty * 4, ob = tx * 8;
    float acc[4][8];
#pragma unroll
    for (int i = 0; i < 4; i++)
#pragma unroll
        for (int j = 0; j < 8; j++) acc[i][j] = 0.0f;

#pragma unroll 4
    for (int f = 0; f < 128; ++f) {
        float4 av = *(const float4*)(Xs + f * 68 + tb);
        float4 u0 = *(const float4*)(Ws + f * 132 + ob);
        float4 u1 = *(const float4*)(Ws + f * 132 + ob + 4);
        float a[4] = {av.x, av.y, av.z, av.w};
        float b[8] = {u0.x, u0.y, u0.z, u0.w, u1.x, u1.y, u1.z, u1.w};
#pragma unroll
        for (int i = 0; i < 4; i++)
#pragma unroll
            for (int j = 0; j < 8; j++) acc[i][j] = fmaf(a[i], b[j], acc[i][j]);
    }
    // last output column (o = 128)
    float accL = 0.0f;
    if (tid < 64 && tid < nt) {
        for (int f = 0; f < 128; ++f) accL += Xs[f * 68 + tid] * Ws[f * 132 + 128];
    }

    const float* beb = be + (size_t)e * Fc;
#pragma unroll
    for (int i = 0; i < 4; i++) {
        int tk = tb + i;
        if (tk < nt) {
            int t = stok[tk]; float g = sg[tk];
#pragma unroll
            for (int j = 0; j < 8; j++)
                atomicAdd(&g_moe[(size_t)t * Fc + ob + j], g * (acc[i][j] + beb[ob + j]));
        }
    }
    if (tid < 64 && tid < nt)
        atomicAdd(&g_moe[(size_t)stok[tid] * Fc + 128], sg[tid] * (accL + beb[128]));
}

// ---------------- 5: moe_loss (deterministic fixed-order reduction) ----------------
// FIXED: no __syncthreads() inside divergent branches.
__global__ void loss_kernel(float* __restrict__ out, int has_loss)
{
    __shared__ float part[256];
    __shared__ float impS[NEc];
    int tid = threadIdx.x;
    int e = tid & 7, chunk = tid >> 3;          // 32 chunks x 8 experts
    const int per = GBc / 32;                   // 200
    float s = 0.0f;
    for (int i = 0; i < per; i++) s += g_imp[(chunk * per + i) * NEc + e];
    part[tid] = s;
    __syncthreads();                            // uniform
    if (tid < NEc) {
        float imp = 0.0f;
        for (int c = 0; c < 32; c++) imp += part[c * NEc + tid];
        impS[tid] = imp;
    }
    __syncthreads();                            // uniform
    if (tid == 0 && has_loss) {
        float mean = 0.0f;
        for (int i = 0; i < NEc; i++) mean += impS[i];
        mean *= (1.0f / NEc);
        float var = 0.0f;
        for (int i = 0; i < NEc; i++) { float d = impS[i] - mean; var += d * d; }
        var *= (1.0f / NEc);
        out[Tc] = var / (mean * mean + 1e-10f);
    }
}

// ---------------- 6: final score + softmax over N ----------------
__global__ __launch_bounds__(128) void final_kernel(
    const float* __restrict__ ninf, const float* __restrict__ Wf,
    float* __restrict__ out)
{
    int bp = blockIdx.x;
    extern __shared__ float sm[];
    float* Ms  = sm;                 // 128*129
    float* Wfs = sm + 128 * 129;     // 132
    float* red = Wfs + 132;          // 8
    int n = threadIdx.x;

    const float* mb = g_moe + (size_t)bp * 128 * Fc;
    for (int i = n; i < 128 * Fc; i += 128) Ms[i] = mb[i];
    for (int i = n; i < Fc; i += 128) Wfs[i] = Wf[i];
    __syncthreads();

    float s = 0.0f;
#pragma unroll 4
    for (int o = 0; o < Fc; ++o) s += Ms[n * Fc + o] * Wfs[o];
    s = 10.0f * tanhf(s) + ninf[(size_t)bp * 128 + n];

    // softmax over 128 threads
    float mx = s;
#pragma unroll
    for (int off = 16; off > 0; off >>= 1)
        mx = fmaxf(mx, __shfl_xor_sync(0xffffffffu, mx, off));
    if ((n & 31) == 0) red[n >> 5] = mx;
    __syncthreads();
    mx = fmaxf(fmaxf(red[0], red[1]), fmaxf(red[2], red[3]));
    float ex = __expf(s - mx);
    float ws = ex;
#pragma unroll
    for (int off = 16; off > 0; off >>= 1)
        ws += __shfl_xor_sync(0xffffffffu, ws, off);
    if ((n & 31) == 0) red[4 + (n >> 5)] = ws;
    __syncthreads();
    float tot = red[4] + red[5] + red[6] + red[7];
    out[(size_t)bp * 128 + n] = ex / tot;
}

// ---------------- launch ----------------
extern "C" void kernel_launch(void* const* d_in, const int* in_sizes, int n_in,
                              void* d_out, int out_size)
{
    const float* nodes  = (const float*)d_in[0];
    const float* routes = (const float*)d_in[1];
    const float* ninf   = (const float*)d_in[2];
    const float* rmask  = (const float*)d_in[3];
    const float* Wq     = (const float*)d_in[4];
    const float* Wk     = (const float*)d_in[5];
    const float* Wv     = (const float*)d_in[6];
    const float* Wg     = (const float*)d_in[7];
    const float* We     = (const float*)d_in[8];
    const float* be     = (const float*)d_in[9];
    const float* Wf     = (const float*)d_in[10];
    float* out = (float*)d_out;

    const int PROJ_SMEM  = (Fc * 128 + Fc * 132) * 4;            // 134160
    const int ATTN_SMEM  = (2048 + 2048 + 128 * 129) * 4;        // 82432
    const int MOE_SMEM   = (128 * 132 + 128 * 68) * 4;           // 102400
    const int FINAL_SMEM = (128 * 129 + 132 + 8) * 4;            // 66608

    cudaFuncSetAttribute(proj_kernel,  cudaFuncAttributeMaxDynamicSharedMemorySize, PROJ_SMEM);
    cudaFuncSetAttribute(attn_kernel,  cudaFuncAttributeMaxDynamicSharedMemorySize, ATTN_SMEM);
    cudaFuncSetAttribute(moe_kernel,   cudaFuncAttributeMaxDynamicSharedMemorySize, MOE_SMEM);
    cudaFuncSetAttribute(final_kernel, cudaFuncAttributeMaxDynamicSharedMemorySize, FINAL_SMEM);

    zero_kernel<<<(Tc * Fc) / 256, 256>>>();                       // 25800 blocks
    proj_kernel<<<3 * BPc, 256, PROJ_SMEM>>>(nodes, routes, Wq, Wk, Wv);
    attn_kernel<<<dim3(BPc, Hc), 128, ATTN_SMEM>>>(rmask, ninf);
    gate_kernel<<<GBc, 256>>>(Wg);
    moe_kernel<<<dim3(800, NEc), 256, MOE_SMEM>>>(We, be);
    loss_kernel<<<1, 256>>>(out, (out_size > Tc) ? 1 : 0);
    final_kernel<<<BPc, 128, FINAL_SMEM>>>(ninf, Wf, out);
}

// round 7
// speedup vs baseline: 1.3509x; 1.3509x over previous
#include <cuda_runtime.h>
#include <math.h>

// ---------------- problem constants ----------------
#define Bc   8
#define Pc   50
#define Nc   128
#define Mc   128
#define Hc   8
#define Dc   16
#define HDc  128          // H*D
#define NEc  8
#define Fc   129          // EMB+1
#define XP   132          // x-tile pitch in fused kernel (16B-aligned rows)
#define Tc   51200        // B*P*N
#define BPc  400          // B*P

// ---------------- scratch (device globals; no allocs allowed) ----------------
__device__ float g_q  [Tc * HDc];
__device__ float g_k  [Tc * HDc];
__device__ float g_v  [Tc * HDc];
__device__ float g_att[Tc * HDc];         // out_concat
__device__ float g_imp[BPc * NEc];        // per-block importance partials
__device__ float g_we [NEc * HDc];        // We[e] @ Wfinal  (8 x 128)
__device__ float g_c  [NEc];              // be[e] . Wfinal

// ---------------- 1: QKV projections (shared-mem SGEMM) ----------------
// grid.x: [0,400) Q (F=128), [400,800) K (F=129), [800,1200) V (F=129)
__global__ __launch_bounds__(256) void proj_kernel(
    const float* __restrict__ nodes, const float* __restrict__ routes,
    const float* __restrict__ Wq, const float* __restrict__ Wk,
    const float* __restrict__ Wv)
{
    int part = blockIdx.x / BPc;
    int tile = blockIdx.x % BPc;
    const float* X; const float* W; float* O; int F;
    if (part == 0)      { X = nodes;  W = Wq; O = g_q; F = 128; }
    else if (part == 1) { X = routes; W = Wk; O = g_k; F = Fc;  }
    else                { X = routes; W = Wv; O = g_v; F = Fc;  }

    extern __shared__ float sm[];
    float* Ws = sm;                  // [F][128]
    float* Xs = sm + Fc * 128;       // [F][132] transposed X

    int tid = threadIdx.x;
    for (int i = tid; i < F * 128; i += 256) Ws[i] = W[i];
    const float* Xb = X + (size_t)tile * 128 * F;
    for (int i = tid; i < 128 * F; i += 256) {
        int r = i / F, f = i % F;
        Xs[f * 132 + r] = Xb[(size_t)r * F + f];
    }
    __syncthreads();

    int tx = tid & 15, ty = tid >> 4;
    int rb = ty * 8, cb = tx * 8;
    float acc[8][8];
#pragma unroll
    for (int i = 0; i < 8; i++)
#pragma unroll
        for (int j = 0; j < 8; j++) acc[i][j] = 0.0f;

#pragma unroll 4
    for (int f = 0; f < 128; ++f) {
        float4 t0 = *(const float4*)(Xs + f * 132 + rb);
        float4 t1 = *(const float4*)(Xs + f * 132 + rb + 4);
        float4 u0 = *(const float4*)(Ws + f * 128 + cb);
        float4 u1 = *(const float4*)(Ws + f * 128 + cb + 4);
        float a[8] = {t0.x, t0.y, t0.z, t0.w, t1.x, t1.y, t1.z, t1.w};
        float b[8] = {u0.x, u0.y, u0.z, u0.w, u1.x, u1.y, u1.z, u1.w};
#pragma unroll
        for (int i = 0; i < 8; i++)
#pragma unroll
            for (int j = 0; j < 8; j++) acc[i][j] = fmaf(a[i], b[j], acc[i][j]);
    }
    if (F > 128) {
        int f = 128;
        float4 t0 = *(const float4*)(Xs + f * 132 + rb);
        float4 t1 = *(const float4*)(Xs + f * 132 + rb + 4);
        float4 u0 = *(const float4*)(Ws + f * 128 + cb);
        float4 u1 = *(const float4*)(Ws + f * 128 + cb + 4);
        float a[8] = {t0.x, t0.y, t0.z, t0.w, t1.x, t1.y, t1.z, t1.w};
        float b[8] = {u0.x, u0.y, u0.z, u0.w, u1.x, u1.y, u1.z, u1.w};
#pragma unroll
        for (int i = 0; i < 8; i++)
#pragma unroll
            for (int j = 0; j < 8; j++) acc[i][j] = fmaf(a[i], b[j], acc[i][j]);
    }

    float* Ob = O + (size_t)tile * 128 * HDc;
#pragma unroll
    for (int i = 0; i < 8; i++) {
        *(float4*)(Ob + (size_t)(rb + i) * HDc + cb) =
            make_float4(acc[i][0], acc[i][1], acc[i][2], acc[i][3]);
        *(float4*)(Ob + (size_t)(rb + i) * HDc + cb + 4) =
            make_float4(acc[i][4], acc[i][5], acc[i][6], acc[i][7]);
    }
}

// ---------------- 2: attention per (bp, head) ----------------
__global__ __launch_bounds__(128) void attn_kernel(
    const float* __restrict__ route_mask, const float* __restrict__ ninf)
{
    int bp = blockIdx.x, h = blockIdx.y;
    extern __shared__ float sm[];
    float* ks = sm;          // 2048
    float* vs = sm + 2048;   // 2048
    float* Ss = sm + 4096;   // 128*129

    int n = threadIdx.x;
    size_t tb = (size_t)bp * 128;

    const float* qp = g_q + (tb + n) * HDc + h * Dc;
    float4 q0 = ((const float4*)qp)[0], q1 = ((const float4*)qp)[1];
    float4 q2 = ((const float4*)qp)[2], q3 = ((const float4*)qp)[3];
    float qr[16] = {q0.x,q0.y,q0.z,q0.w, q1.x,q1.y,q1.z,q1.w,
                    q2.x,q2.y,q2.z,q2.w, q3.x,q3.y,q3.z,q3.w};
    {
        const float4* kp = (const float4*)(g_k + (tb + n) * HDc + h * Dc);
        const float4* vp = (const float4*)(g_v + (tb + n) * HDc + h * Dc);
        float4* kd = (float4*)(ks + n * 16);
        float4* vd = (float4*)(vs + n * 16);
#pragma unroll
        for (int j = 0; j < 4; j++) { kd[j] = kp[j]; vd[j] = vp[j]; }
    }
    const float* rm = route_mask + (size_t)bp * 128 * 128;
    for (int i = n; i < 128 * 128; i += 128) {
        int r = i >> 7, m = i & 127;
        Ss[r * 129 + m] = rm[i];
    }
    __syncthreads();

#pragma unroll 4
    for (int m = 0; m < 128; ++m) {
        const float4* kp = (const float4*)(ks + m * 16);
        float4 k0 = kp[0], k1 = kp[1], k2 = kp[2], k3 = kp[3];
        float s = qr[0]*k0.x + qr[1]*k0.y + qr[2]*k0.z + qr[3]*k0.w
                + qr[4]*k1.x + qr[5]*k1.y + qr[6]*k1.z + qr[7]*k1.w
                + qr[8]*k2.x + qr[9]*k2.y + qr[10]*k2.z + qr[11]*k2.w
                + qr[12]*k3.x + qr[13]*k3.y + qr[14]*k3.z + qr[15]*k3.w;
        Ss[n * 129 + m] = s * 0.25f + Ss[n * 129 + m];
    }

    float mx = -1e30f;
    for (int m = 0; m < 128; ++m) mx = fmaxf(mx, Ss[n * 129 + m]);
    float sum = 0.0f;
    float acc[16];
#pragma unroll
    for (int d = 0; d < 16; d++) acc[d] = 0.0f;
#pragma unroll 2
    for (int m = 0; m < 128; ++m) {
        float pe = __expf(Ss[n * 129 + m] - mx);
        sum += pe;
        const float4* vp = (const float4*)(vs + m * 16);
        float4 v0 = vp[0], v1 = vp[1], v2 = vp[2], v3 = vp[3];
        acc[0]+=pe*v0.x; acc[1]+=pe*v0.y; acc[2]+=pe*v0.z; acc[3]+=pe*v0.w;
        acc[4]+=pe*v1.x; acc[5]+=pe*v1.y; acc[6]+=pe*v1.z; acc[7]+=pe*v1.w;
        acc[8]+=pe*v2.x; acc[9]+=pe*v2.y; acc[10]+=pe*v2.z; acc[11]+=pe*v2.w;
        acc[12]+=pe*v3.x; acc[13]+=pe*v3.y; acc[14]+=pe*v3.z; acc[15]+=pe*v3.w;
    }
    float keep = (ninf[tb + n] == 0.0f) ? 1.0f : 0.0f;
    float inv = keep / sum;
    float* op = g_att + (tb + n) * HDc + h * Dc;
    ((float4*)op)[0] = make_float4(acc[0]*inv, acc[1]*inv, acc[2]*inv, acc[3]*inv);
    ((float4*)op)[1] = make_float4(acc[4]*inv, acc[5]*inv, acc[6]*inv, acc[7]*inv);
    ((float4*)op)[2] = make_float4(acc[8]*inv, acc[9]*inv, acc[10]*inv, acc[11]*inv);
    ((float4*)op)[3] = make_float4(acc[12]*inv, acc[13]*inv, acc[14]*inv, acc[15]*inv);
}

// ---------------- 3: precompute we = We @ Wfinal, c = be . Wfinal ----------------
__global__ __launch_bounds__(128) void prep_kernel(
    const float* __restrict__ We, const float* __restrict__ be,
    const float* __restrict__ Wf)
{
    extern __shared__ float sm[];
    float* tileS = sm;            // [128][129] (scalar access only)
    float* wfs   = sm + 128 * Fc; // 132
    int e = blockIdx.x, tid = threadIdx.x;

    const float* Wb = We + (size_t)e * 128 * Fc;
    for (int i = tid; i < 128 * Fc; i += 128) tileS[i] = Wb[i];
    for (int i = tid; i < Fc; i += 128) wfs[i] = Wf[i];
    __syncthreads();

    float s = 0.0f;
#pragma unroll 4
    for (int o = 0; o < Fc; ++o) s += tileS[tid * Fc + o] * wfs[o];
    g_we[e * HDc + tid] = s;

    if (tid == 0) {
        float c = 0.0f;
        const float* bb = be + (size_t)e * Fc;
        for (int o = 0; o < Fc; ++o) c += bb[o] * wfs[o];
        g_c[e] = c;
    }
}

// ---------------- 4: fused gate + MoE-collapsed score + softmax ----------------
// One block per bp; thread n = token n. x tile pitch XP=132 -> 16B-aligned rows.
__global__ __launch_bounds__(128) void fused_kernel(
    const float* __restrict__ ninf, const float* __restrict__ Wg,
    float* __restrict__ out)
{
    int bp = blockIdx.x, n = threadIdx.x;
    extern __shared__ float sm[];
    float* Xs  = sm;                    // 128*132 (aligned rows)
    float* Wgs = sm + 128 * XP;         // 8*128
    float* Wes = Wgs + NEc * HDc;       // 8*128
    float* cS  = Wes + NEc * HDc;       // 8
    float* red = cS + NEc;              // 8
    int*   sE  = (int*)(red + NEc);     // 128*2
    float* sG  = (float*)(sE + 256);    // 128*2

    // stage x tile (coalesced), weights
    const float* attb = g_att + (size_t)bp * 128 * HDc;
    for (int i = n; i < 128 * 128; i += 128)
        Xs[(i >> 7) * XP + (i & 127)] = attb[i];
    for (int i = n; i < NEc * HDc; i += 128) {
        int ee = i >> 7, f = i & 127;
        Wgs[i] = Wg[f * NEc + ee];      // transpose
        Wes[i] = g_we[i];               // already [e][f]
    }
    if (n < NEc) cS[n] = g_c[n];
    __syncthreads();

    // 16 dot products of length 128 (8 gate logits + 8 expert scores)
    float dg[NEc], de[NEc];
#pragma unroll
    for (int e = 0; e < NEc; e++) { dg[e] = 0.0f; de[e] = 0.0f; }
    const float4* xr = (const float4*)(Xs + n * XP);   // XP*4 % 16 == 0 -> aligned
#pragma unroll 4
    for (int o4 = 0; o4 < 32; ++o4) {
        float4 xv = xr[o4];
#pragma unroll
        for (int e = 0; e < NEc; e++) {
            float4 wg = ((const float4*)(Wgs + e * HDc))[o4];   // broadcast
            float4 we = ((const float4*)(Wes + e * HDc))[o4];   // broadcast
            dg[e] += xv.x*wg.x + xv.y*wg.y + xv.z*wg.z + xv.w*wg.w;
            de[e] += xv.x*we.x + xv.y*we.y + xv.z*we.z + xv.w*we.w;
        }
    }

    // top-2 of 8 + softmax gates
    float v1 = -1e30f, v2 = -1e30f; int i1 = 0, i2 = 0;
#pragma unroll
    for (int e = 0; e < NEc; e++) {
        float v = dg[e];
        if (v > v1)      { v2 = v1; i2 = i1; v1 = v; i1 = e; }
        else if (v > v2) { v2 = v;  i2 = e; }
    }
    float e2x = __expf(v2 - v1);
    float den = 1.0f + e2x;
    float g1 = 1.0f / den, g2 = e2x / den;

    sE[n * 2 + 0] = i1; sG[n * 2 + 0] = g1;
    sE[n * 2 + 1] = i2; sG[n * 2 + 1] = g2;

    // collapsed MoE + final projection
    float s = g1 * (de[i1] + cS[i1]) + g2 * (de[i2] + cS[i2]);
    s = 10.0f * tanhf(s) + ninf[(size_t)bp * 128 + n];

    __syncthreads();   // sE/sG visible

    // importance partials (fixed order -> deterministic)
    if (n < NEc) {
        float imp = 0.0f;
        for (int t = 0; t < 128; ++t) {
            if (sE[t * 2 + 0] == n) imp += sG[t * 2 + 0];
            if (sE[t * 2 + 1] == n) imp += sG[t * 2 + 1];
        }
        g_imp[bp * NEc + n] = imp;
    }

    // softmax over the 128 tokens of this bp
    float mx = s;
#pragma unroll
    for (int off = 16; off > 0; off >>= 1)
        mx = fmaxf(mx, __shfl_xor_sync(0xffffffffu, mx, off));
    if ((n & 31) == 0) red[n >> 5] = mx;
    __syncthreads();
    mx = fmaxf(fmaxf(red[0], red[1]), fmaxf(red[2], red[3]));
    float ex = __expf(s - mx);
    float ws = ex;
#pragma unroll
    for (int off = 16; off > 0; off >>= 1)
        ws += __shfl_xor_sync(0xffffffffu, ws, off);
    if ((n & 31) == 0) red[4 + (n >> 5)] = ws;
    __syncthreads();
    float tot = red[4] + red[5] + red[6] + red[7];
    out[(size_t)bp * 128 + n] = ex / tot;
}

// ---------------- 5: moe_loss from 400x8 partials ----------------
__global__ void loss_kernel(float* __restrict__ out, int has_loss)
{
    __shared__ float part[64];
    __shared__ float impS[NEc];
    int tid = threadIdx.x;                    // 64 threads
    int e = tid & 7, seg = tid >> 3;          // 8 segs x 8 experts
    float s = 0.0f;
    for (int i = seg * 50; i < (seg + 1) * 50; ++i) s += g_imp[i * NEc + e];
    part[tid] = s;
    __syncthreads();
    if (tid < NEc) {
        float imp = 0.0f;
        for (int c = 0; c < 8; ++c) imp += part[c * NEc + tid];
        impS[tid] = imp;
    }
    __syncthreads();
    if (tid == 0 && has_loss) {
        float mean = 0.0f;
        for (int i = 0; i < NEc; i++) mean += impS[i];
        mean *= (1.0f / NEc);
        float var = 0.0f;
        for (int i = 0; i < NEc; i++) { float d = impS[i] - mean; var += d * d; }
        var *= (1.0f / NEc);
        out[Tc] = var / (mean * mean + 1e-10f);
    }
}

// ---------------- launch ----------------
extern "C" void kernel_launch(void* const* d_in, const int* in_sizes, int n_in,
                              void* d_out, int out_size)
{
    const float* nodes  = (const float*)d_in[0];
    const float* routes = (const float*)d_in[1];
    const float* ninf   = (const float*)d_in[2];
    const float* rmask  = (const float*)d_in[3];
    const float* Wq     = (const float*)d_in[4];
    const float* Wk     = (const float*)d_in[5];
    const float* Wv     = (const float*)d_in[6];
    const float* Wg     = (const float*)d_in[7];
    const float* We     = (const float*)d_in[8];
    const float* be     = (const float*)d_in[9];
    const float* Wf     = (const float*)d_in[10];
    float* out = (float*)d_out;

    const int PROJ_SMEM  = (Fc * 128 + Fc * 132) * 4;                 // 134160
    const int ATTN_SMEM  = (2048 + 2048 + 128 * 129) * 4;             // 82432
    const int PREP_SMEM  = (128 * Fc + 132) * 4;                      // 66576
    const int FUSED_SMEM = (128 * XP + 2 * NEc * HDc + NEc + NEc) * 4
                           + 256 * 4 + 256 * 4;                       // ~78KB

    cudaFuncSetAttribute(proj_kernel,  cudaFuncAttributeMaxDynamicSharedMemorySize, PROJ_SMEM);
    cudaFuncSetAttribute(attn_kernel,  cudaFuncAttributeMaxDynamicSharedMemorySize, ATTN_SMEM);
    cudaFuncSetAttribute(prep_kernel,  cudaFuncAttributeMaxDynamicSharedMemorySize, PREP_SMEM);
    cudaFuncSetAttribute(fused_kernel, cudaFuncAttributeMaxDynamicSharedMemorySize, FUSED_SMEM);

    prep_kernel<<<NEc, 128, PREP_SMEM>>>(We, be, Wf);
    proj_kernel<<<3 * BPc, 256, PROJ_SMEM>>>(nodes, routes, Wq, Wk, Wv);
    attn_kernel<<<dim3(BPc, Hc), 128, ATTN_SMEM>>>(rmask, ninf);
    fused_kernel<<<BPc, 128, FUSED_SMEM>>>(ninf, Wg, out);
    loss_kernel<<<1, 64>>>(out, (out_size > Tc) ? 1 : 0);
}